// round 5
// baseline (speedup 1.0000x reference)
#include <cuda_runtime.h>
#include <math.h>

#define GRID 128
#define NTHR 256
#define Bv   128
#define Sv   256
#define HDv  512

// Persistent device scratch (allocation-free).
__device__ float    g_X[Bv * Sv];        // current SDE state
__device__ float    g_H[2 * Bv * HDv];   // tanh hidden: [0]=drift, [1]=sigma
__device__ float    g_P[4 * Bv * Sv];    // layer2 partials [mat*2 + kchunk]
__device__ unsigned g_bar;               // grid barrier counter (monotone)

// Reset the barrier counter before each run (separate node -> stream-ordered).
__global__ void k_zero() { g_bar = 0u; }

// Software grid barrier: all GRID CTAs co-resident (128 <= 148 SMs, 1 CTA/SM fits).
__device__ __forceinline__ void grid_bar(unsigned goal) {
    __syncthreads();
    if (threadIdx.x == 0) {
        __threadfence();                 // release: publish our writes
        atomicAdd(&g_bar, 1u);
        while (*((volatile unsigned*)&g_bar) < goal) { }
        __threadfence();                 // acquire: see others' writes
    }
    __syncthreads();
}

// ---------------------------------------------------------------------------
// 32x32 output tile GEMM, K=256 starting at kbase, split across the CTA's two
// 128-thread halves (kh). Each half: 4x2 register micro-tile, k-tiles of 32,
// register-prefetch pipelined. Cross-half reduce in smem at the end.
// A is cross-CTA data -> __ldcg; W is read-only weights -> __ldg.
// ---------------------------------------------------------------------------
template<bool TANH>
__device__ __forceinline__ void gemm32(
    const float* __restrict__ A, int lda,
    const float* __restrict__ W, int ldw,
    const float* __restrict__ bias,
    float* __restrict__ Out, int ldo,
    int m0, int n0, int kbase, float* sm)
{
    const int t    = threadIdx.x;
    const int kh   = t >> 7;         // K-half: 0 or 1
    const int tt   = t & 127;
    const int tm   = tt >> 4;        // 0..7  -> rows m0 + tm*4 + i
    const int tn   = tt & 15;        // 0..15 -> cols n0 + tn*2 + j
    const int row0 = tt >> 3;        // 0..15 (loader role)
    const int c40  = (tt & 7) << 2;  // 0,4,...,28

    float* As = sm + kh * (32 * 36);                 // [k][m] transposed, pad 36
    float* Bs = sm + 2 * (32 * 36) + kh * (32 * 32); // [k][n]
    const int ks = kbase + (kh << 7);

    float a00=0.f,a01=0.f,a10=0.f,a11=0.f,a20=0.f,a21=0.f,a30=0.f,a31=0.f;

    const float* Arow0 = A + (m0 + row0)      * lda;
    const float* Arow1 = A + (m0 + row0 + 16) * lda;

    float4 pa0, pa1, pb0, pb1;
    {   // prefetch k-tile 0
        const int k0 = ks;
        pa0 = __ldcg((const float4*)(Arow0 + k0 + c40));
        pa1 = __ldcg((const float4*)(Arow1 + k0 + c40));
        pb0 = __ldg ((const float4*)(W + (k0 + row0)      * ldw + n0 + c40));
        pb1 = __ldg ((const float4*)(W + (k0 + row0 + 16) * ldw + n0 + c40));
    }

#pragma unroll
    for (int kt = 0; kt < 4; kt++) {
        // stage prefetched tile into smem (A transposed; conflict-free banks)
        As[(c40 + 0) * 36 + row0]      = pa0.x;
        As[(c40 + 1) * 36 + row0]      = pa0.y;
        As[(c40 + 2) * 36 + row0]      = pa0.z;
        As[(c40 + 3) * 36 + row0]      = pa0.w;
        As[(c40 + 0) * 36 + row0 + 16] = pa1.x;
        As[(c40 + 1) * 36 + row0 + 16] = pa1.y;
        As[(c40 + 2) * 36 + row0 + 16] = pa1.z;
        As[(c40 + 3) * 36 + row0 + 16] = pa1.w;
        *((float4*)(Bs + row0 * 32 + c40))        = pb0;
        *((float4*)(Bs + (row0 + 16) * 32 + c40)) = pb1;
        __syncthreads();

        if (kt < 3) {   // issue next tile's LDGs before compute (hide L2 latency)
            const int k0 = ks + (kt + 1) * 32;
            pa0 = __ldcg((const float4*)(Arow0 + k0 + c40));
            pa1 = __ldcg((const float4*)(Arow1 + k0 + c40));
            pb0 = __ldg ((const float4*)(W + (k0 + row0)      * ldw + n0 + c40));
            pb1 = __ldg ((const float4*)(W + (k0 + row0 + 16) * ldw + n0 + c40));
        }

#pragma unroll
        for (int k = 0; k < 32; k++) {
            float4 a = *((const float4*)(As + k * 36 + tm * 4));
            float2 b = *((const float2*)(Bs + k * 32 + tn * 2));
            a00 = fmaf(a.x, b.x, a00); a01 = fmaf(a.x, b.y, a01);
            a10 = fmaf(a.y, b.x, a10); a11 = fmaf(a.y, b.y, a11);
            a20 = fmaf(a.z, b.x, a20); a21 = fmaf(a.z, b.y, a21);
            a30 = fmaf(a.w, b.x, a30); a31 = fmaf(a.w, b.y, a31);
        }
        __syncthreads();
    }

    // cross-half reduction via smem (reuse As region)
    float* R = sm;
    if (kh) {
        *((float4*)(R + tt * 8))     = make_float4(a00, a01, a10, a11);
        *((float4*)(R + tt * 8 + 4)) = make_float4(a20, a21, a30, a31);
    }
    __syncthreads();
    if (!kh) {
        float4 r0 = *((const float4*)(R + tt * 8));
        float4 r1 = *((const float4*)(R + tt * 8 + 4));
        float v00=a00+r0.x, v01=a01+r0.y, v10=a10+r0.z, v11=a11+r0.w;
        float v20=a20+r1.x, v21=a21+r1.y, v30=a30+r1.z, v31=a31+r1.w;
        if (TANH) {
            float b0 = __ldg(bias + n0 + tn * 2);
            float b1 = __ldg(bias + n0 + tn * 2 + 1);
            v00 = tanhf(v00 + b0); v01 = tanhf(v01 + b1);
            v10 = tanhf(v10 + b0); v11 = tanhf(v11 + b1);
            v20 = tanhf(v20 + b0); v21 = tanhf(v21 + b1);
            v30 = tanhf(v30 + b0); v31 = tanhf(v31 + b1);
        }
        float* o = Out + (m0 + tm * 4) * ldo + n0 + tn * 2;
        __stcg((float2*)(o),           make_float2(v00, v01));
        __stcg((float2*)(o + ldo),     make_float2(v10, v11));
        __stcg((float2*)(o + 2 * ldo), make_float2(v20, v21));
        __stcg((float2*)(o + 3 * ldo), make_float2(v30, v31));
    }
}

// ---------------------------------------------------------------------------
// One persistent kernel: init, then 1000x { L1 | bar | L2 | bar | update | bar }.
// ---------------------------------------------------------------------------
__global__ __launch_bounds__(NTHR) void k_fsde(
    const float* __restrict__ x0,
    const float* __restrict__ Wd1, const float* __restrict__ bd1,
    const float* __restrict__ Wd2, const float* __restrict__ bd2,
    const float* __restrict__ Ws1, const float* __restrict__ bs1,
    const float* __restrict__ Ws2, const float* __restrict__ bs2,
    const float* __restrict__ raw_h,
    const float* __restrict__ fgn,
    float* __restrict__ out, int N)
{
    __shared__ float sm[2 * 32 * 36 + 2 * 32 * 32];

    const int bx = blockIdx.x;
    const int t  = threadIdx.x;
    const int gi = bx * NTHR + t;          // 0..32767, one state element/thread
    const int b  = gi >> 8;
    const int s  = gi & (Sv - 1);

    // init: state register + publish X + trajectory slice 0
    float x = __ldg(x0 + gi);
    __stcg(&g_X[gi], x);
    out[(size_t)b * (size_t)(N + 1) * Sv + s] = x;

    const float dt = 1.0f / (float)N;
    const float rh = __ldg(raw_h);
    const float Hh = 0.98f / (1.0f + expf(-rh)) + 0.01f;
    const float nscale = (float)exp((double)Hh * log(1.0 / (double)N)); // dt^H

    // L1 tile decode: 2 mats x 4 row-tiles x 16 col-tiles = 128 CTAs
    const int mat1 = bx >> 6;
    const int m01  = ((bx >> 4) & 3) * 32;
    const int n01  = (bx & 15) * 32;
    const float* W1 = mat1 ? Ws1 : Wd1;
    const float* b1 = mat1 ? bs1 : bd1;
    float* H1 = g_H + mat1 * (Bv * HDv);

    // L2 tile decode: 2 mats x 2 K-chunks x 4 row-tiles x 8 col-tiles = 128 CTAs
    const int mat2 = bx >> 6;
    const int q    = bx & 63;
    const int kc   = q >> 5;
    const int m02  = ((q >> 3) & 3) * 32;
    const int n02  = (q & 7) * 32;
    const float* W2 = mat2 ? Ws2 : Wd2;
    const float* A2 = g_H + mat2 * (Bv * HDv);
    float* P2 = g_P + (mat2 * 2 + kc) * (Bv * Sv);
    const int kb2 = kc * 256;

    unsigned goal = GRID;
    grid_bar(goal); goal += GRID;          // X published

    for (int step = 0; step < N; step++) {
        // Phase 1: H = tanh(X @ W1 + b1)
        gemm32<true >(g_X, Sv, W1, HDv, b1, H1, HDv, m01, n01, 0, sm);
        grid_bar(goal); goal += GRID;

        // Phase 2: P = H[:, kchunk] @ W2[kchunk, :]
        gemm32<false>(A2, HDv, W2, Sv, (const float*)0, P2, Sv, m02, n02, kb2, sm);
        grid_bar(goal); goal += GRID;

        // Phase 3: state update (x stays in register)
        float drift = __ldcg(&g_P[gi])              + __ldcg(&g_P[Bv * Sv + gi])     + __ldg(bd2 + s);
        float sig   = __ldcg(&g_P[2 * Bv * Sv + gi]) + __ldcg(&g_P[3 * Bv * Sv + gi]) + __ldg(bs2 + s);
        float fg    = __ldg(fgn + (size_t)step * (Bv * Sv) + gi);
        x = x + drift * dt;
        x = x + sig * (nscale * fg);
        __stcg(&g_X[gi], x);
        out[(size_t)b * (size_t)(N + 1) * Sv + (size_t)(step + 1) * Sv + s] = x;
        grid_bar(goal); goal += GRID;      // X ready for next step's L1
    }
}

// ---------------------------------------------------------------------------
// Host launcher: 2 graph nodes total, fully capturable, allocation-free.
// ---------------------------------------------------------------------------
extern "C" void kernel_launch(void* const* d_in, const int* in_sizes, int n_in,
                              void* d_out, int out_size) {
    const float* x0    = (const float*)d_in[0];
    const float* Wd1   = (const float*)d_in[1];
    const float* bd1   = (const float*)d_in[2];
    const float* Wd2   = (const float*)d_in[3];
    const float* bd2   = (const float*)d_in[4];
    const float* Ws1   = (const float*)d_in[5];
    const float* bs1   = (const float*)d_in[6];
    const float* Ws2   = (const float*)d_in[7];
    const float* bs2   = (const float*)d_in[8];
    const float* raw_h = (const float*)d_in[9];
    const float* fgn   = (const float*)d_in[10];
    float* out = (float*)d_out;

    const int N = in_sizes[10] / in_sizes[0];   // (N*B*S)/(B*S) = 1000

    k_zero<<<1, 1>>>();
    k_fsde<<<GRID, NTHR>>>(x0, Wd1, bd1, Wd2, bd2, Ws1, bs1, Ws2, bs2,
                           raw_h, fgn, out, N);
}

// round 10
// speedup vs baseline: 1.1026x; 1.1026x over previous
#include <cuda_runtime.h>
#include <math.h>

#define GRID 128
#define NTHR 512
#define Bv   128
#define Sv   256
#define HDv  512
#define APAD 134   // As row pad: 134 % 32 = 6 -> a-loads hit 4 distinct banks

// Persistent device scratch (allocation-free).
__device__ float    g_X[Bv * Sv];        // current SDE state
__device__ float    g_H[2 * Bv * HDv];   // tanh hidden: [0]=drift, [1]=sigma
__device__ float    g_P[4 * Bv * Sv];    // layer2 partials [mat*2 + kchunk]
__device__ unsigned g_bar;               // grid barrier counter (monotone)

__global__ void k_zero() { g_bar = 0u; }

// Software grid barrier: 128 CTAs x 512 thr, all co-resident (128 <= 148 SMs).
__device__ __forceinline__ void grid_bar(unsigned goal) {
    __syncthreads();
    if (threadIdx.x == 0) {
        __threadfence();                 // release
        atomicAdd(&g_bar, 1u);
        while (*((volatile unsigned*)&g_bar) < goal) { }
        __threadfence();                 // acquire
    }
    __syncthreads();
}

// ---------------------------------------------------------------------------
// 32x32 output tile, K=256 (two staged passes of 128), 8 K-groups x 64 threads,
// 4x4 register micro-tile per thread, smem reduction across groups.
// A = cross-CTA data (ldcg), W = weights (ldg).
// smem layout: As[32][APAD] (17152B) | Bs[128][32] (16384B); reduce reuses both.
// ---------------------------------------------------------------------------
template<bool TANH>
__device__ __forceinline__ void gemm32(
    const float* __restrict__ A, int lda,
    const float* __restrict__ W, int ldw,
    const float* __restrict__ bias,
    float* __restrict__ Out, int ldo,
    int m0, int n0, int kbase, float* sm)
{
    float* As = sm;               // [32][APAD]
    float* Bs = sm + 32 * APAD;   // [128][32]
    const int t  = threadIdx.x;
    const int g  = t >> 6;        // K-group 0..7
    const int tt = t & 63;
    const int tm = tt >> 3;       // 0..7 -> rows m0 + tm*4 + i
    const int tn = tt & 7;        // 0..7 -> cols n0 + tn*4 + j

    float acc[4][4];
#pragma unroll
    for (int i = 0; i < 4; i++)
#pragma unroll
        for (int j = 0; j < 4; j++) acc[i][j] = 0.0f;

#pragma unroll
    for (int p = 0; p < 2; p++) {
        const int kp = kbase + p * 128;
        // Stage A[32 x 128] (row-major, padded) and B[128 x 32].
#pragma unroll
        for (int it = 0; it < 2; it++) {
            int idx = it * 512 + t;
            int row = idx >> 5;
            int c4  = (idx & 31) << 2;
            float4 va = __ldcg((const float4*)(A + (m0 + row) * lda + kp + c4));
            *((float2*)(As + row * APAD + c4))     = make_float2(va.x, va.y);
            *((float2*)(As + row * APAD + c4 + 2)) = make_float2(va.z, va.w);
            int kr  = idx >> 3;
            int c4b = (idx & 7) << 2;
            *((float4*)(Bs + kr * 32 + c4b)) =
                __ldg((const float4*)(W + (kp + kr) * ldw + n0 + c4b));
        }
        __syncthreads();

        const int k0 = g * 16;
#pragma unroll
        for (int kk = 0; kk < 16; kk++) {
            const int k = k0 + kk;
            float a0 = As[(tm * 4 + 0) * APAD + k];
            float a1 = As[(tm * 4 + 1) * APAD + k];
            float a2 = As[(tm * 4 + 2) * APAD + k];
            float a3 = As[(tm * 4 + 3) * APAD + k];
            float4 b = *((const float4*)(Bs + k * 32 + tn * 4));
            acc[0][0] = fmaf(a0, b.x, acc[0][0]); acc[0][1] = fmaf(a0, b.y, acc[0][1]);
            acc[0][2] = fmaf(a0, b.z, acc[0][2]); acc[0][3] = fmaf(a0, b.w, acc[0][3]);
            acc[1][0] = fmaf(a1, b.x, acc[1][0]); acc[1][1] = fmaf(a1, b.y, acc[1][1]);
            acc[1][2] = fmaf(a1, b.z, acc[1][2]); acc[1][3] = fmaf(a1, b.w, acc[1][3]);
            acc[2][0] = fmaf(a2, b.x, acc[2][0]); acc[2][1] = fmaf(a2, b.y, acc[2][1]);
            acc[2][2] = fmaf(a2, b.z, acc[2][2]); acc[2][3] = fmaf(a2, b.w, acc[2][3]);
            acc[3][0] = fmaf(a3, b.x, acc[3][0]); acc[3][1] = fmaf(a3, b.y, acc[3][1]);
            acc[3][2] = fmaf(a3, b.z, acc[3][2]); acc[3][3] = fmaf(a3, b.w, acc[3][3]);
        }
        __syncthreads();
    }

    // Reduce the 8 K-group partials via smem (reuses As/Bs region: 32KB).
    float* R = sm;
#pragma unroll
    for (int i = 0; i < 4; i++) {
        *((float4*)(R + g * 1024 + (tm * 4 + i) * 32 + tn * 4)) =
            make_float4(acc[i][0], acc[i][1], acc[i][2], acc[i][3]);
    }
    __syncthreads();
#pragma unroll
    for (int h = 0; h < 2; h++) {
        int e = h * 512 + t;                 // 0..1023
        float s = R[e];
#pragma unroll
        for (int gg = 1; gg < 8; gg++) s += R[gg * 1024 + e];
        int m = e >> 5, n = e & 31;
        if (TANH) s = tanhf(s + __ldg(bias + n0 + n));
        __stcg(Out + (m0 + m) * ldo + n0 + n, s);
    }
    __syncthreads();   // protect sm before next phase restages
}

// ---------------------------------------------------------------------------
// One persistent kernel: init, then N x { L1 | bar | L2 | bar | update | bar }.
// ---------------------------------------------------------------------------
__global__ __launch_bounds__(NTHR) void k_fsde(
    const float* __restrict__ x0,
    const float* __restrict__ Wd1, const float* __restrict__ bd1,
    const float* __restrict__ Wd2, const float* __restrict__ bd2,
    const float* __restrict__ Ws1, const float* __restrict__ bs1,
    const float* __restrict__ Ws2, const float* __restrict__ bs2,
    const float* __restrict__ raw_h,
    const float* __restrict__ fgn,
    float* __restrict__ out, int N)
{
    __shared__ float sm[32 * APAD + 128 * 32];   // 33536 B

    const int bx = blockIdx.x;
    const int t  = threadIdx.x;

    // --- per-thread state element (threads t < 256 own one element) ---
    const int gi = bx * 256 + (t & 255);   // 0..32767
    const int b  = gi >> 8;
    const int s  = gi & (Sv - 1);
    float x = 0.0f;
    if (t < 256) {
        x = __ldg(x0 + gi);
        __stcg(&g_X[gi], x);
        out[(size_t)b * (size_t)(N + 1) * Sv + s] = x;
    }

    const float dt = 1.0f / (float)N;
    const float rh = __ldg(raw_h);
    const float Hh = 0.98f / (1.0f + expf(-rh)) + 0.01f;
    const float nscale = (float)exp((double)Hh * log(1.0 / (double)N)); // dt^H

    // L1 decode: 2 mats x 4 mtiles x 16 ntiles = 128 CTAs
    const int mat1 = bx >> 6;
    const int m01  = ((bx >> 4) & 3) * 32;
    const int n01  = (bx & 15) * 32;
    const float* W1 = mat1 ? Ws1 : Wd1;
    const float* b1 = mat1 ? bs1 : bd1;
    float* H1 = g_H + mat1 * (Bv * HDv);

    // L2 decode: 2 mats x 2 kc x 4 mtiles x 8 ntiles = 128 CTAs
    const int mat2 = bx >> 6;
    const int q    = bx & 63;
    const int kc   = q >> 5;
    const int m02  = ((q >> 3) & 3) * 32;
    const int n02  = (q & 7) * 32;
    const float* W2 = mat2 ? Ws2 : Wd2;
    const float* A2 = g_H + mat2 * (Bv * HDv);
    float* P2 = g_P + (mat2 * 2 + kc) * (Bv * Sv);
    const int kb2 = kc * 256;

    unsigned goal = GRID;
    grid_bar(goal); goal += GRID;          // X published

    for (int step = 0; step < N; step++) {
        // Phase 1: H = tanh(X @ W1 + b1)
        gemm32<true >(g_X, Sv, W1, HDv, b1, H1, HDv, m01, n01, 0, sm);
        grid_bar(goal); goal += GRID;

        // Phase 2: P = H[:, kchunk] @ W2[kchunk, :]
        gemm32<false>(A2, HDv, W2, Sv, (const float*)0, P2, Sv, m02, n02, kb2, sm);
        grid_bar(goal); goal += GRID;

        // Phase 3: state update (x stays in register)
        if (t < 256) {
            float drift = __ldcg(&g_P[gi])               + __ldcg(&g_P[Bv * Sv + gi])
                        + __ldg(bd2 + s);
            float sig   = __ldcg(&g_P[2 * Bv * Sv + gi]) + __ldcg(&g_P[3 * Bv * Sv + gi])
                        + __ldg(bs2 + s);
            float fg    = __ldcs(fgn + (size_t)step * (Bv * Sv) + gi);
            x = x + drift * dt;
            x = x + sig * (nscale * fg);
            __stcg(&g_X[gi], x);
            __stcs(out + (size_t)b * (size_t)(N + 1) * Sv
                       + (size_t)(step + 1) * Sv + s, x);
        }
        grid_bar(goal); goal += GRID;      // X ready for next step's L1
    }
}

// ---------------------------------------------------------------------------
// Host launcher: 2 graph nodes, fully capturable, allocation-free.
// ---------------------------------------------------------------------------
extern "C" void kernel_launch(void* const* d_in, const int* in_sizes, int n_in,
                              void* d_out, int out_size) {
    const float* x0    = (const float*)d_in[0];
    const float* Wd1   = (const float*)d_in[1];
    const float* bd1   = (const float*)d_in[2];
    const float* Wd2   = (const float*)d_in[3];
    const float* bd2   = (const float*)d_in[4];
    const float* Ws1   = (const float*)d_in[5];
    const float* bs1   = (const float*)d_in[6];
    const float* Ws2   = (const float*)d_in[7];
    const float* bs2   = (const float*)d_in[8];
    const float* raw_h = (const float*)d_in[9];
    const float* fgn   = (const float*)d_in[10];
    float* out = (float*)d_out;

    const int N = in_sizes[10] / in_sizes[0];   // 1000

    k_zero<<<1, 1>>>();
    k_fsde<<<GRID, NTHR>>>(x0, Wd1, bd1, Wd2, bd2, Ws1, bs1, Ws2, bs2,
                           raw_h, fgn, out, N);
}